// round 5
// baseline (speedup 1.0000x reference)
#include <cuda_runtime.h>

// Rician NLL fused elementwise + full reduction.
//   out = -sum( log(I0(e*o*inv_var)) - 0.5*inv_var*e^2 )
// 2 x 33.55M fp32 reads (268 MB) -> HBM-bound streaming reduction.

#define NB 1184   // 8 blocks per SM on 148 SMs
#define NT 256

__device__ float d_partials[NB];

// log(I0(x)) via Abramowitz & Stegun 9.8.1 / 9.8.2 (fp32, rel err ~2e-7).
// Inputs here are always in [0,1) (uniform*uniform), so the small branch is
// the only one taken; large branch kept for robustness.
__device__ __forceinline__ float log_i0f(float x) {
    float ax = fabsf(x);
    if (ax < 3.75f) {
        float t = ax * (1.0f / 3.75f);
        t *= t;
        float p = 1.0f + t * (3.5156229f + t * (3.0899424f + t * (1.2067492f
                + t * (0.2659732f + t * (0.0360768f + t * 0.0045813f)))));
        return __logf(p);
    } else {
        float ti = 3.75f / ax;
        float p = 0.39894228f + ti * (0.01328592f + ti * (0.00225319f
                + ti * (-0.00157565f + ti * (0.00916281f + ti * (-0.02057706f
                + ti * (0.02635537f + ti * (-0.01647633f + ti * 0.00392377f)))))));
        return ax - 0.5f * __logf(ax) + __logf(p);
    }
}

__global__ __launch_bounds__(NT)
void nll_partial_kernel(const float* __restrict__ est,
                        const float* __restrict__ obs,
                        const float* __restrict__ std_noise,
                        int n) {
    const float s = std_noise[0];
    const float inv_var  = 1.0f / (s * s);
    const float half_inv = 0.5f * inv_var;

    float acc = 0.0f;
    const int n4 = n >> 2;
    const float4* __restrict__ e4 = (const float4*)est;
    const float4* __restrict__ o4 = (const float4*)obs;

    const int stride = gridDim.x * blockDim.x;
    for (int i = blockIdx.x * blockDim.x + threadIdx.x; i < n4; i += stride) {
        float4 e = e4[i];
        float4 o = o4[i];
        acc += log_i0f(e.x * o.x * inv_var) - half_inv * e.x * e.x;
        acc += log_i0f(e.y * o.y * inv_var) - half_inv * e.y * e.y;
        acc += log_i0f(e.z * o.z * inv_var) - half_inv * e.z * e.z;
        acc += log_i0f(e.w * o.w * inv_var) - half_inv * e.w * e.w;
    }
    // scalar tail (empty for n = 2^25, kept for generality)
    for (int i = (n4 << 2) + blockIdx.x * blockDim.x + threadIdx.x; i < n; i += stride) {
        float e = est[i], o = obs[i];
        acc += log_i0f(e * o * inv_var) - half_inv * e * e;
    }

    // deterministic block reduction: warp shuffle tree + shared
    __shared__ float sdata[NT / 32];
    #pragma unroll
    for (int off = 16; off > 0; off >>= 1)
        acc += __shfl_down_sync(0xffffffffu, acc, off);
    const int lane = threadIdx.x & 31;
    const int wid  = threadIdx.x >> 5;
    if (lane == 0) sdata[wid] = acc;
    __syncthreads();
    if (wid == 0) {
        acc = (lane < NT / 32) ? sdata[lane] : 0.0f;
        #pragma unroll
        for (int off = 16; off > 0; off >>= 1)
            acc += __shfl_down_sync(0xffffffffu, acc, off);
        if (lane == 0) d_partials[blockIdx.x] = acc;
    }
}

__global__ __launch_bounds__(1024)
void nll_final_kernel(float* __restrict__ out) {
    __shared__ float sdata[32];
    float acc = 0.0f;
    for (int i = threadIdx.x; i < NB; i += 1024)
        acc += d_partials[i];
    #pragma unroll
    for (int off = 16; off > 0; off >>= 1)
        acc += __shfl_down_sync(0xffffffffu, acc, off);
    const int lane = threadIdx.x & 31;
    const int wid  = threadIdx.x >> 5;
    if (lane == 0) sdata[wid] = acc;
    __syncthreads();
    if (wid == 0) {
        acc = sdata[lane];  // 1024 threads -> exactly 32 warps, all slots valid
        #pragma unroll
        for (int off = 16; off > 0; off >>= 1)
            acc += __shfl_down_sync(0xffffffffu, acc, off);
        if (lane == 0) out[0] = -acc;
    }
}

extern "C" void kernel_launch(void* const* d_in, const int* in_sizes, int n_in,
                              void* d_out, int out_size) {
    const float* est = (const float*)d_in[0];
    const float* obs = (const float*)d_in[1];
    const float* sn  = (const float*)d_in[2];
    const int n = in_sizes[0];

    nll_partial_kernel<<<NB, NT>>>(est, obs, sn, n);
    nll_final_kernel<<<1, 1024>>>((float*)d_out);
}